// round 6
// baseline (speedup 1.0000x reference)
#include <cuda_runtime.h>
#include <cuda_bf16.h>
#include <cstdint>

#define NN 50000
#define EE 800000
#define DD 96
#define DD4 24
#define NPAD 53248          // 13 tiles * 4096, padded for int4 scan

// scratch
__device__ float g_support[(size_t)NN * DD];   // X @ W
__device__ int   g_count[NPAD];                // histogram -> write-ptr (in place)
__device__ int   g_rowptr[NN + 1];
__device__ int2  g_edge[EE];                   // sorted (col, val_bits)

// ---- f32x2 helpers -------------------------------------------------------
__device__ __forceinline__ void fma2(unsigned long long& d,
                                     unsigned long long a,
                                     unsigned long long b) {
    asm("fma.rn.f32x2 %0, %1, %2, %0;" : "+l"(d) : "l"(a), "l"(b));
}
__device__ __forceinline__ unsigned long long pack2(float lo, float hi) {
    unsigned long long r;
    asm("mov.b64 %0, {%1, %2};" : "=l"(r) : "f"(lo), "f"(hi));
    return r;
}

// ---------------------------------------------------------------------------
// GEMM: support[N,96] = X[N,96] @ W[96,96], f32x2 packed FMA.
// Also zeroes g_count (fused; hist runs in the next kernel, stream-ordered).
// ---------------------------------------------------------------------------
__global__ __launch_bounds__(96) void gemm_kernel(const float* __restrict__ x,
                                                  const float* __restrict__ w) {
    __shared__ float Ws[DD * DD];      // [k][col]
    __shared__ float Xt[DD * 32];      // [k][row]

    const int tid = threadIdx.x;       // 0..95
    const int row0 = blockIdx.x * 32;

    // fused zero of histogram counters (incl. scan padding)
    {
        int i = blockIdx.x * 96 + tid;
        if (i < NPAD) g_count[i] = 0;
    }

    // load W: 2304 float4, 24 per thread
    {
        const float4* w4 = reinterpret_cast<const float4*>(w);
        float4* ws4 = reinterpret_cast<float4*>(Ws);
#pragma unroll
        for (int i = 0; i < 24; i++) ws4[tid + i * 96] = w4[tid + i * 96];
    }
    // load X tile transposed
    {
        const int r = tid & 31;
        const int wp = tid >> 5;
        const int gr = row0 + r;
        const float4* x4 = reinterpret_cast<const float4*>(x);
#pragma unroll
        for (int i = 0; i < 8; i++) {
            int k4 = wp + 3 * i;
            float4 v = make_float4(0.f, 0.f, 0.f, 0.f);
            if (gr < NN) v = x4[(size_t)gr * DD4 + k4];
            Xt[(k4 * 4 + 0) * 32 + r] = v.x;
            Xt[(k4 * 4 + 1) * 32 + r] = v.y;
            Xt[(k4 * 4 + 2) * 32 + r] = v.z;
            Xt[(k4 * 4 + 3) * 32 + r] = v.w;
        }
    }
    __syncthreads();

    const int rt = tid / DD4;
    const int ct = tid % DD4;

    unsigned long long acc[4][4];
#pragma unroll
    for (int i = 0; i < 4; i++)
#pragma unroll
        for (int j = 0; j < 4; j++) acc[i][j] = 0ull;

    const float4* ws4 = reinterpret_cast<const float4*>(Ws);
#pragma unroll 4
    for (int k = 0; k < DD; k++) {
        const double* xp = reinterpret_cast<const double*>(Xt + k * 32 + rt * 8);
        unsigned long long x0 = __double_as_longlong(xp[0]);
        unsigned long long x1 = __double_as_longlong(xp[1]);
        unsigned long long x2 = __double_as_longlong(xp[2]);
        unsigned long long x3 = __double_as_longlong(xp[3]);
        float4 wv = ws4[k * DD4 + ct];
        unsigned long long w0 = pack2(wv.x, wv.x);
        unsigned long long w1 = pack2(wv.y, wv.y);
        unsigned long long w2 = pack2(wv.z, wv.z);
        unsigned long long w3 = pack2(wv.w, wv.w);
        fma2(acc[0][0], x0, w0); fma2(acc[0][1], x0, w1); fma2(acc[0][2], x0, w2); fma2(acc[0][3], x0, w3);
        fma2(acc[1][0], x1, w0); fma2(acc[1][1], x1, w1); fma2(acc[1][2], x1, w2); fma2(acc[1][3], x1, w3);
        fma2(acc[2][0], x2, w0); fma2(acc[2][1], x2, w1); fma2(acc[2][2], x2, w2); fma2(acc[2][3], x2, w3);
        fma2(acc[3][0], x3, w0); fma2(acc[3][1], x3, w1); fma2(acc[3][2], x3, w2); fma2(acc[3][3], x3, w3);
    }

    float4* s4 = reinterpret_cast<float4*>(g_support);
#pragma unroll
    for (int i = 0; i < 4; i++) {
        int grl = row0 + rt * 8 + 2 * i;
        float4 lo, hi;
        lo.x = __uint_as_float((unsigned)(acc[i][0]));
        lo.y = __uint_as_float((unsigned)(acc[i][1]));
        lo.z = __uint_as_float((unsigned)(acc[i][2]));
        lo.w = __uint_as_float((unsigned)(acc[i][3]));
        hi.x = __uint_as_float((unsigned)(acc[i][0] >> 32));
        hi.y = __uint_as_float((unsigned)(acc[i][1] >> 32));
        hi.z = __uint_as_float((unsigned)(acc[i][2] >> 32));
        hi.w = __uint_as_float((unsigned)(acc[i][3] >> 32));
        if (grl < NN)     s4[(size_t)grl * DD4 + ct] = lo;
        if (grl + 1 < NN) s4[(size_t)(grl + 1) * DD4 + ct] = hi;
    }
}

// ---------------------------------------------------------------------------
// Histogram of edge rows
// ---------------------------------------------------------------------------
__global__ void hist_kernel(const int* __restrict__ erow) {
    int e = blockIdx.x * 256 + threadIdx.x;
    if (e < EE) atomicAdd(&g_count[erow[e]], 1);
}

// ---------------------------------------------------------------------------
// Single-block exclusive scan over g_count[0..NPAD) -> g_rowptr.
// Also leaves g_count[i] = rowptr[i] in place (write pointers for build).
// 1024 threads, int4 per thread per tile, 13 tiles.
// ---------------------------------------------------------------------------
__global__ __launch_bounds__(1024) void scan_kernel() {
    __shared__ int warpsum[32];
    __shared__ int blocktot;

    const int t = threadIdx.x;
    const int lane = t & 31;
    const int wid = t >> 5;

    if (t == 0) g_rowptr[NN] = EE;

    int carry = 0;
    const int4* c4 = reinterpret_cast<const int4*>(g_count);

#pragma unroll
    for (int tile = 0; tile < 13; tile++) {
        int idx4 = tile * 1024 + t;
        int4 v = c4[idx4];
        int s = v.x + v.y + v.z + v.w;

        // warp inclusive scan
        int inc = s;
#pragma unroll
        for (int off = 1; off < 32; off <<= 1) {
            int n = __shfl_up_sync(0xffffffffu, inc, off);
            if (lane >= off) inc += n;
        }
        if (lane == 31) warpsum[wid] = inc;
        __syncthreads();

        if (wid == 0) {
            int ws = warpsum[lane];
            int winc = ws;
#pragma unroll
            for (int off = 1; off < 32; off <<= 1) {
                int n = __shfl_up_sync(0xffffffffu, winc, off);
                if (lane >= off) winc += n;
            }
            warpsum[lane] = winc - ws;          // exclusive warp offsets
            if (lane == 31) blocktot = winc;    // tile total
        }
        __syncthreads();

        int base = carry + warpsum[wid] + (inc - s);
        int i0 = idx4 * 4;
        if (i0 < NN) {
            int4 o;
            o.x = base;
            o.y = base + v.x;
            o.z = o.y + v.y;
            o.w = o.z + v.z;
            reinterpret_cast<int4*>(g_rowptr)[idx4] = o;
            reinterpret_cast<int4*>(g_count)[idx4] = o;   // same-thread rewrite: safe
        }
        carry += blocktot;
        __syncthreads();   // protect warpsum/blocktot reuse
    }
}

// ---------------------------------------------------------------------------
// Bucket-place edges: g_edge[pos] = (col, val_bits)
// ---------------------------------------------------------------------------
__global__ void build_kernel(const int* __restrict__ erow,
                             const int* __restrict__ ecol,
                             const float* __restrict__ eval_) {
    int e = blockIdx.x * 256 + threadIdx.x;
    if (e >= EE) return;
    int r = erow[e];
    int pos = atomicAdd(&g_count[r], 1);
    g_edge[pos] = make_int2(ecol[e], __float_as_int(eval_[e]));
}

// ---------------------------------------------------------------------------
// SpMM: warp per row, uniform edge read (no shfl), bias fused, one store.
// ---------------------------------------------------------------------------
__global__ __launch_bounds__(256) void spmm_kernel(const float* __restrict__ b,
                                                   float* __restrict__ out) {
    int row = blockIdx.x * 8 + (threadIdx.x >> 5);
    if (row >= NN) return;
    int lane = threadIdx.x & 31;

    int start = g_rowptr[row];
    int end   = g_rowptr[row + 1];

    float4 acc = make_float4(0.f, 0.f, 0.f, 0.f);
    const float4* s4 = reinterpret_cast<const float4*>(g_support);

    for (int e = start; e < end; e++) {
        int2 ev = g_edge[e];                 // uniform across warp (broadcast)
        float v = __int_as_float(ev.y);
        if (lane < DD4) {
            float4 s = s4[(size_t)ev.x * DD4 + lane];
            acc.x += v * s.x; acc.y += v * s.y;
            acc.z += v * s.z; acc.w += v * s.w;
        }
    }

    if (lane < DD4) {
        float4 bb = reinterpret_cast<const float4*>(b)[lane];
        float4 r;
        r.x = acc.x + bb.x; r.y = acc.y + bb.y;
        r.z = acc.z + bb.z; r.w = acc.w + bb.w;
        reinterpret_cast<float4*>(out)[(size_t)row * DD4 + lane] = r;
    }
}

extern "C" void kernel_launch(void* const* d_in, const int* in_sizes, int n_in,
                              void* d_out, int out_size) {
    const float* x     = (const float*)d_in[0];
    const int*   erow  = (const int*)d_in[1];
    const int*   ecol  = (const int*)d_in[2];
    const float* evalv = (const float*)d_in[3];
    const float* w     = (const float*)d_in[4];
    const float* b     = (const float*)d_in[5];
    float* out = (float*)d_out;

    gemm_kernel<<<(NN + 31) / 32, 96>>>(x, w);            // + zero counters
    hist_kernel<<<(EE + 255) / 256, 256>>>(erow);
    scan_kernel<<<1, 1024>>>();
    build_kernel<<<(EE + 255) / 256, 256>>>(erow, ecol, evalv);
    spmm_kernel<<<(NN + 7) / 8, 256>>>(b, out);
}

// round 7
// speedup vs baseline: 1.1236x; 1.1236x over previous
#include <cuda_runtime.h>
#include <cuda_bf16.h>
#include <cstdint>

#define NN 50000
#define EE 800000
#define DD 96
#define DD4 24
#define NPAD 53248          // 13 tiles * 4096, padded for int4 scan

// scratch (zero-initialized at load; g_count kept zeroed call-to-call by spmm)
__device__ float g_support[(size_t)NN * DD];   // X @ W
__device__ int   g_count[NPAD];                // histogram -> write-ptr (in place)
__device__ int   g_rowptr[NN + 1];
__device__ int2  g_edge[EE];                   // sorted (col, val_bits)

// ---- f32x2 helpers -------------------------------------------------------
__device__ __forceinline__ void fma2(unsigned long long& d,
                                     unsigned long long a,
                                     unsigned long long b) {
    asm("fma.rn.f32x2 %0, %1, %2, %0;" : "+l"(d) : "l"(a), "l"(b));
}
__device__ __forceinline__ unsigned long long pack2(float lo, float hi) {
    unsigned long long r;
    asm("mov.b64 %0, {%1, %2};" : "=l"(r) : "f"(lo), "f"(hi));
    return r;
}

// ---------------------------------------------------------------------------
// GEMM: support[N,96] = X[N,96] @ W[96,96], f32x2 packed FMA.
// Tail: fused row histogram (g_count is zero on entry; REDs drain in the
// shadow of the FMA work / kernel drain).
// ---------------------------------------------------------------------------
__global__ __launch_bounds__(96) void gemm_kernel(const float* __restrict__ x,
                                                  const float* __restrict__ w,
                                                  const int* __restrict__ erow) {
    __shared__ float Ws[DD * DD];      // [k][col]
    __shared__ float Xt[DD * 32];      // [k][row]

    const int tid = threadIdx.x;       // 0..95
    const int row0 = blockIdx.x * 32;

    // load W: 2304 float4, 24 per thread
    {
        const float4* w4 = reinterpret_cast<const float4*>(w);
        float4* ws4 = reinterpret_cast<float4*>(Ws);
#pragma unroll
        for (int i = 0; i < 24; i++) ws4[tid + i * 96] = w4[tid + i * 96];
    }
    // load X tile transposed
    {
        const int r = tid & 31;
        const int wp = tid >> 5;
        const int gr = row0 + r;
        const float4* x4 = reinterpret_cast<const float4*>(x);
#pragma unroll
        for (int i = 0; i < 8; i++) {
            int k4 = wp + 3 * i;
            float4 v = make_float4(0.f, 0.f, 0.f, 0.f);
            if (gr < NN) v = x4[(size_t)gr * DD4 + k4];
            Xt[(k4 * 4 + 0) * 32 + r] = v.x;
            Xt[(k4 * 4 + 1) * 32 + r] = v.y;
            Xt[(k4 * 4 + 2) * 32 + r] = v.z;
            Xt[(k4 * 4 + 3) * 32 + r] = v.w;
        }
    }
    __syncthreads();

    const int rt = tid / DD4;
    const int ct = tid % DD4;

    unsigned long long acc[4][4];
#pragma unroll
    for (int i = 0; i < 4; i++)
#pragma unroll
        for (int j = 0; j < 4; j++) acc[i][j] = 0ull;

    const float4* ws4 = reinterpret_cast<const float4*>(Ws);
#pragma unroll 4
    for (int k = 0; k < DD; k++) {
        const double* xp = reinterpret_cast<const double*>(Xt + k * 32 + rt * 8);
        unsigned long long x0 = __double_as_longlong(xp[0]);
        unsigned long long x1 = __double_as_longlong(xp[1]);
        unsigned long long x2 = __double_as_longlong(xp[2]);
        unsigned long long x3 = __double_as_longlong(xp[3]);
        float4 wv = ws4[k * DD4 + ct];
        unsigned long long w0 = pack2(wv.x, wv.x);
        unsigned long long w1 = pack2(wv.y, wv.y);
        unsigned long long w2 = pack2(wv.z, wv.z);
        unsigned long long w3 = pack2(wv.w, wv.w);
        fma2(acc[0][0], x0, w0); fma2(acc[0][1], x0, w1); fma2(acc[0][2], x0, w2); fma2(acc[0][3], x0, w3);
        fma2(acc[1][0], x1, w0); fma2(acc[1][1], x1, w1); fma2(acc[1][2], x1, w2); fma2(acc[1][3], x1, w3);
        fma2(acc[2][0], x2, w0); fma2(acc[2][1], x2, w1); fma2(acc[2][2], x2, w2); fma2(acc[2][3], x2, w3);
        fma2(acc[3][0], x3, w0); fma2(acc[3][1], x3, w1); fma2(acc[3][2], x3, w2); fma2(acc[3][3], x3, w3);
    }

    float4* s4 = reinterpret_cast<float4*>(g_support);
#pragma unroll
    for (int i = 0; i < 4; i++) {
        int grl = row0 + rt * 8 + 2 * i;
        float4 lo, hi;
        lo.x = __uint_as_float((unsigned)(acc[i][0]));
        lo.y = __uint_as_float((unsigned)(acc[i][1]));
        lo.z = __uint_as_float((unsigned)(acc[i][2]));
        lo.w = __uint_as_float((unsigned)(acc[i][3]));
        hi.x = __uint_as_float((unsigned)(acc[i][0] >> 32));
        hi.y = __uint_as_float((unsigned)(acc[i][1] >> 32));
        hi.z = __uint_as_float((unsigned)(acc[i][2] >> 32));
        hi.w = __uint_as_float((unsigned)(acc[i][3] >> 32));
        if (grl < NN)     s4[(size_t)grl * DD4 + ct] = lo;
        if (grl + 1 < NN) s4[(size_t)(grl + 1) * DD4 + ct] = hi;
    }

    // ---- fused histogram tail (fire-and-forget REDs) ----
    {
        const int T = gridDim.x * 96;              // 1563*96 = 150048
        for (int e = blockIdx.x * 96 + tid; e < EE; e += T)
            atomicAdd(&g_count[erow[e]], 1);       // no return use -> RED
    }
}

// ---------------------------------------------------------------------------
// Single-block exclusive scan over g_count[0..NPAD) -> g_rowptr.
// Also leaves g_count[i] = rowptr[i] in place (write pointers for build).
// ---------------------------------------------------------------------------
__global__ __launch_bounds__(1024) void scan_kernel() {
    __shared__ int warpsum[32];
    __shared__ int blocktot;

    const int t = threadIdx.x;
    const int lane = t & 31;
    const int wid = t >> 5;

    if (t == 0) g_rowptr[NN] = EE;

    int carry = 0;
    const int4* c4 = reinterpret_cast<const int4*>(g_count);

#pragma unroll
    for (int tile = 0; tile < 13; tile++) {
        int idx4 = tile * 1024 + t;
        int4 v = c4[idx4];
        int s = v.x + v.y + v.z + v.w;

        int inc = s;
#pragma unroll
        for (int off = 1; off < 32; off <<= 1) {
            int n = __shfl_up_sync(0xffffffffu, inc, off);
            if (lane >= off) inc += n;
        }
        if (lane == 31) warpsum[wid] = inc;
        __syncthreads();

        if (wid == 0) {
            int ws = warpsum[lane];
            int winc = ws;
#pragma unroll
            for (int off = 1; off < 32; off <<= 1) {
                int n = __shfl_up_sync(0xffffffffu, winc, off);
                if (lane >= off) winc += n;
            }
            warpsum[lane] = winc - ws;
            if (lane == 31) blocktot = winc;
        }
        __syncthreads();

        int base = carry + warpsum[wid] + (inc - s);
        int i0 = idx4 * 4;
        if (i0 < NN) {
            int4 o;
            o.x = base;
            o.y = base + v.x;
            o.z = o.y + v.y;
            o.w = o.z + v.z;
            reinterpret_cast<int4*>(g_rowptr)[idx4] = o;
            reinterpret_cast<int4*>(g_count)[idx4] = o;   // same-thread rewrite
        }
        carry += blocktot;
        __syncthreads();
    }
}

// ---------------------------------------------------------------------------
// Bucket-place edges: g_edge[pos] = (col, val_bits)
// ---------------------------------------------------------------------------
__global__ void build_kernel(const int* __restrict__ erow,
                             const int* __restrict__ ecol,
                             const float* __restrict__ eval_) {
    int e = blockIdx.x * 256 + threadIdx.x;
    if (e >= EE) return;
    int r = erow[e];
    int pos = atomicAdd(&g_count[r], 1);
    g_edge[pos] = make_int2(ecol[e], __float_as_int(eval_[e]));
}

// ---------------------------------------------------------------------------
// SpMM: warp per row, shfl-staged edge batches (MLP across 32 gathers),
// bias fused, one store. Side job: re-zero g_count for the next call.
// ---------------------------------------------------------------------------
__global__ __launch_bounds__(256) void spmm_kernel(const float* __restrict__ b,
                                                   float* __restrict__ out) {
    // re-zero counters (covers NPAD with first 208 blocks; grid is 6250)
    {
        int zi = blockIdx.x * 256 + threadIdx.x;
        if (zi < NPAD) g_count[zi] = 0;
    }

    int row = blockIdx.x * 8 + (threadIdx.x >> 5);
    if (row >= NN) return;
    int lane = threadIdx.x & 31;

    int start = g_rowptr[row];
    int end   = g_rowptr[row + 1];

    float4 acc = make_float4(0.f, 0.f, 0.f, 0.f);
    const float4* s4 = reinterpret_cast<const float4*>(g_support);

    for (int e0 = start; e0 < end; e0 += 32) {
        int n = min(32, end - e0);
        int2 ev = make_int2(0, 0);
        if (lane < n) ev = g_edge[e0 + lane];
        for (int i = 0; i < n; i++) {
            int   ci = __shfl_sync(0xffffffffu, ev.x, i);
            float vi = __int_as_float(__shfl_sync(0xffffffffu, ev.y, i));
            if (lane < DD4) {
                float4 s = s4[(size_t)ci * DD4 + lane];
                acc.x += vi * s.x; acc.y += vi * s.y;
                acc.z += vi * s.z; acc.w += vi * s.w;
            }
        }
    }

    if (lane < DD4) {
        float4 bb = reinterpret_cast<const float4*>(b)[lane];
        float4 r;
        r.x = acc.x + bb.x; r.y = acc.y + bb.y;
        r.z = acc.z + bb.z; r.w = acc.w + bb.w;
        reinterpret_cast<float4*>(out)[(size_t)row * DD4 + lane] = r;
    }
}

extern "C" void kernel_launch(void* const* d_in, const int* in_sizes, int n_in,
                              void* d_out, int out_size) {
    const float* x     = (const float*)d_in[0];
    const int*   erow  = (const int*)d_in[1];
    const int*   ecol  = (const int*)d_in[2];
    const float* evalv = (const float*)d_in[3];
    const float* w     = (const float*)d_in[4];
    const float* b     = (const float*)d_in[5];
    float* out = (float*)d_out;

    gemm_kernel<<<(NN + 31) / 32, 96>>>(x, w, erow);   // + fused histogram
    scan_kernel<<<1, 1024>>>();
    build_kernel<<<(EE + 255) / 256, 256>>>(erow, ecol, evalv);
    spmm_kernel<<<(NN + 7) / 8, 256>>>(b, out);        // + re-zero counters
}